// round 14
// baseline (speedup 1.0000x reference)
#include <cuda_runtime.h>

// Fixed problem shapes
#define BB 16
#define TT 288
#define NN 4096
#define HH 10
#define RR 16
#define TCIN 8                      // t-chunks INSIDE a k1 block
#define TPC (TT / TCIN)             // 36
#define X1 64                       // k1 n-groups (32 float4 cols each)
#define NBLKS1 (X1 * BB)            // 1024 k1 blocks
#define PREDBLKS 640                // 163840 float4 outputs / 256
#define NBLKS2 (PREDBLKS + BB)      // 656
#define FIX 1048576.0               // 2^20 fixed-point scale

// Scratch (fully rewritten / accumulated each replay; totals+counter reset by
// the counter-elected epilogue block -> graph-replay safe).
__device__ float4 g_fin[BB][NN / 2];     // FINAL (s0,c0,s1,c1) per node pair
__device__ unsigned long long g_tot_s;   // global valid-sum, fixed-point 2^20
__device__ unsigned long long g_tot_c;   // global valid-count
__device__ unsigned int g_ctr;           // epilogue reset election

// ---------------------------------------------------------------------------
// Kernel 1: heavy streaming pass over 151MB, T-reduction completed in-block.
// grid (64,16) = 1024 blocks x 256 thr. Thread (col=tid&31, tc=tid>>5):
// 36 strided float4 loads; smem-reduce 8 t-chunks -> final (s,c) per pair.
// Block totals go into TWO integer global atomics (deterministic, order-free).
// ---------------------------------------------------------------------------
__global__ void __launch_bounds__(256) k1_main(const float4* __restrict__ data) {
    const int tid  = threadIdx.x;
    const int col  = tid & 31;
    const int tc   = tid >> 5;            // 0..7
    const int x    = blockIdx.x;
    const int b    = blockIdx.y;
    const int colg = x * 32 + col;        // global float4 column [0, 2048)

    const float4* __restrict__ p =
        data + (size_t)(b * TT + tc * TPC) * (NN / 2) + colg;

    float s0 = 0.f, s1 = 0.f, c0 = 0.f, c1 = 0.f;
    #pragma unroll 6
    for (int t = 0; t < TPC; ++t) {
        float4 v = __ldcs(p);
        p += NN / 2;
        if (v.x != -1.0f) { s0 += v.x; c0 += 1.0f; }
        if (v.z != -1.0f) { s1 += v.z; c1 += 1.0f; }
    }

    __shared__ float4 sh[TCIN][32];
    sh[tc][col] = make_float4(s0, c0, s1, c1);
    __syncthreads();

    if (tid < 32) {
        float4 a = sh[0][tid];
        float fs0 = a.x, fc0 = a.y, fs1 = a.z, fc1 = a.w;
        #pragma unroll
        for (int k = 1; k < TCIN; ++k) {
            float4 v = sh[k][tid];
            fs0 += v.x; fc0 += v.y; fs1 += v.z; fc1 += v.w;
        }
        g_fin[b][x * 32 + tid] = make_float4(fs0, fc0, fs1, fc1);

        float s = fs0 + fs1;
        float c = fc0 + fc1;
        #pragma unroll
        for (int o = 16; o > 0; o >>= 1) {
            s += __shfl_down_sync(0xffffffffu, s, o);
            c += __shfl_down_sync(0xffffffffu, c, o);
        }
        if (tid == 0) {
            // fixed-point accumulate: integer atomics = deterministic
            atomicAdd(&g_tot_s,
                      (unsigned long long)(long long)((double)s * FIX + 0.5));
            atomicAdd(&g_tot_c, (unsigned long long)(c + 0.5f));
        }
    }
}

// ---------------------------------------------------------------------------
// Kernel 2 (epilogue): 656 independent blocks x 256 thr. Minimal chains.
//   x < 640 : pred_speed — per thread: 2 float4 loads -> 8 FMA -> 1 float4 st
//   x >= 640: regional for batch b = x-640 (warp-split smem atomics)
// gm = one scalar pair load + divide. Totals/counter reset by the elected
// block (every block increments only after gm is computed from its loads).
// ---------------------------------------------------------------------------
__global__ void __launch_bounds__(256) k2_epilogue(const int* __restrict__ cid,
                                                   float* __restrict__ out) {
    const int tid = threadIdx.x;
    const int x   = blockIdx.x;

    __shared__ float sh_gm;
    if (tid == 0) {
        const unsigned long long su = g_tot_s;
        const unsigned long long cu = g_tot_c;
        const float s = (float)((double)(long long)su * (1.0 / FIX));
        const float c = (float)cu;
        sh_gm = s / fmaxf(c, 1.0f);        // depends on loads -> they complete
    }
    __syncthreads();
    const float gm = sh_gm;

    // reset election (only after this block's gm is done)
    if (tid == 0) {
        if (atomicAdd(&g_ctr, 1u) == NBLKS2 - 1) {
            g_tot_s = 0ull;
            g_tot_c = 0ull;
            g_ctr   = 0u;
        }
    }

    const float invT = 1.0f / (float)TT;

    if (x < PREDBLKS) {
        // ---- pred_speed: one float4 output element per thread ----
        const int o  = x * 256 + tid;      // float4 index into pred_speed
        const int qq = o & 1023;           // float4 col within [b][h] row
        const int bh = o >> 10;            // 0..159
        const int b  = bh / 10;

        const float4 f0 = g_fin[b][qq * 2];
        const float4 f1 = g_fin[b][qq * 2 + 1];
        float4 r;
        r.x = (f0.x + ((float)TT - f0.y) * gm) * invT;
        r.y = (f0.z + ((float)TT - f0.w) * gm) * invT;
        r.z = (f1.x + ((float)TT - f1.y) * gm) * invT;
        r.w = (f1.z + ((float)TT - f1.w) * gm) * invT;
        ((float4*)out)[o] = r;
        return;
    }

    // ---- regional for batch b ----
    const int b   = x - PREDBLKS;
    const int wid = tid >> 5, lane = tid & 31;

    __shared__ float rs[8][RR];
    __shared__ float rc[8][RR];
    if (lane < RR) { rs[wid][lane] = 0.f; rc[wid][lane] = 0.f; }
    __syncthreads();

    #pragma unroll
    for (int k = 0; k < 8; ++k) {
        const int q = k * 256 + tid;          // float4 column (2 nodes)
        const float4 f = g_fin[b][q];
        const float m0 = (f.x + ((float)TT - f.y) * gm) * invT;
        const float m1 = (f.z + ((float)TT - f.w) * gm) * invT;
        const int2 cc = ((const int2*)cid)[q];
        atomicAdd(&rs[wid][cc.x], m0);
        atomicAdd(&rc[wid][cc.x], 1.0f);
        atomicAdd(&rs[wid][cc.y], m1);
        atomicAdd(&rc[wid][cc.y], 1.0f);
    }
    __syncthreads();

    if (tid < RR) {
        float a = 0.f, n = 0.f;
        #pragma unroll
        for (int w = 0; w < 8; ++w) { a += rs[w][tid]; n += rc[w][tid]; }
        const float val = a / fmaxf(n, 1.0f);

        float* __restrict__ ro = out + (size_t)BB * HH * NN;
        #pragma unroll
        for (int h = 0; h < HH; ++h)
            ro[((size_t)b * HH + h) * RR + tid] = val;
    }
}

// ---------------------------------------------------------------------------
extern "C" void kernel_launch(void* const* d_in, const int* in_sizes, int n_in,
                              void* d_out, int out_size) {
    const float4* data = (const float4*)d_in[0];
    const int*    cid  = (const int*)d_in[1];
    float*        out  = (float*)d_out;

    dim3 g1(X1, BB);          // (64,16) = 1024 blocks
    k1_main<<<g1, 256>>>(data);
    k2_epilogue<<<NBLKS2, 256>>>(cid, out);   // 656 independent blocks
}